// round 2
// baseline (speedup 1.0000x reference)
#include <cuda_runtime.h>

// ExodusNet: per-timestep dense (32 -> 1), ExpLeak scan, LIF scan with
// SingleSpike + MembraneSubtract.  x: (B, 32, 100) fp32 (t innermost),
// w: (32) fp32, out: (B, 100) fp32 of 0/1 spikes.

namespace {

constexpr int T_STEPS    = 100;
constexpr int F_DIM      = 32;
constexpr int ROW_FLOATS = F_DIM * T_STEPS;       // 3200 floats per batch row
constexpr int BPB        = 128;                   // batch elements per block
constexpr int THREADS    = 256;                   // 8 warps
constexpr int B_PER_WARP = BPB / (THREADS / 32);  // 16
constexpr int SM_STRIDE  = 101;                   // conflict-free phase-2 reads

__device__ __forceinline__ float alpha_f() { return (float)0.9048374180359595; }
__device__ __forceinline__ float one_m_a() { return (float)(1.0 - 0.9048374180359595); }

__global__ __launch_bounds__(THREADS)
void exodus_kernel(const float* __restrict__ x,
                   const float* __restrict__ w,
                   float* __restrict__ out,
                   int B)
{
    __shared__ float wsh[F_DIM];
    extern __shared__ float ish[];                // BPB * SM_STRIDE floats

    const int tid  = threadIdx.x;
    const int warp = tid >> 5;
    const int lane = tid & 31;
    const int b0   = blockIdx.x * BPB;

    if (tid < F_DIM) wsh[tid] = w[tid];
    __syncthreads();

    // ---------------- Phase 1: weighted input currents i[b][t] ----------------
    // Warp-per-b; lane owns timestep t = 32*c + lane (scalar, fully coalesced:
    // 32 lanes x 4B = 128B per f per chunk).  All 32 scalar loads of an f-batch
    // are independent (32 in flight per warp at 1 reg each), so DRAM latency is
    // hidden across 32 warps/SM.  Accumulation is a single sequential f-chain
    // (bitwise identical to the rel_err==0 ordering).
    {
        const int bl_begin = warp * B_PER_WARP;
        for (int bl = bl_begin; bl < bl_begin + B_PER_WARP; ++bl) {
            const int b = b0 + bl;
            if (b >= B) break;
            const float* base = x + (size_t)b * ROW_FLOATS;
            float* ip = ish + bl * SM_STRIDE;
            #pragma unroll
            for (int c = 0; c < 4; ++c) {
                const int t = c * 32 + lane;
                if (t < T_STEPS) {
                    float xa[F_DIM];
                    #pragma unroll
                    for (int f = 0; f < F_DIM; ++f)
                        xa[f] = base[f * T_STEPS + t];
                    float acc = 0.f;
                    #pragma unroll
                    for (int f = 0; f < F_DIM; ++f)
                        acc = fmaf(xa[f], wsh[f], acc);
                    ip[t] = acc;
                }
            }
        }
    }
    __syncthreads();

    // ---------------- Phase 2: sequential scans, one thread per b --------------
    // syn[t] = a*syn[t-1] + i[t]
    // v[t]   = a*v[t-1] + (1-a)*syn[t];  s = (v >= 1);  v -= s
    if (tid < BPB && (b0 + tid) < B) {
        float* ip = ish + tid * SM_STRIDE;
        float syn = 0.f, v = 0.f;
        #pragma unroll 4
        for (int t = 0; t < T_STEPS; ++t) {
            const float i = ip[t];
            syn = fmaf(alpha_f(), syn, i);
            v   = fmaf(alpha_f(), v, one_m_a() * syn);
            const float s = (v >= 1.0f) ? 1.0f : 0.0f;
            v -= s;
            ip[t] = s;
        }
    }
    __syncthreads();

    // ---------------- Phase 3: coalesced spike write-out -----------------------
    {
        const int bl_begin = warp * B_PER_WARP;
        for (int bl = bl_begin; bl < bl_begin + B_PER_WARP; ++bl) {
            const int b = b0 + bl;
            if (b >= B) break;
            float* op       = out + (size_t)b * T_STEPS;
            const float* ip = ish + bl * SM_STRIDE;
            #pragma unroll
            for (int j = 0; j < 4; ++j) {
                const int t = lane + 32 * j;
                if (t < T_STEPS) op[t] = ip[t];
            }
        }
    }
}

} // namespace

extern "C" void kernel_launch(void* const* d_in, const int* in_sizes, int n_in,
                              void* d_out, int out_size)
{
    const float* x = (const float*)d_in[0];
    const float* w = (const float*)d_in[1];
    float* out     = (float*)d_out;

    const int B = in_sizes[0] / ROW_FLOATS;   // 32768

    const int smem_bytes = BPB * SM_STRIDE * (int)sizeof(float);  // 51712
    cudaFuncSetAttribute(exodus_kernel,
                         cudaFuncAttributeMaxDynamicSharedMemorySize, smem_bytes);

    const int grid = (B + BPB - 1) / BPB;
    exodus_kernel<<<grid, THREADS, smem_bytes>>>(x, w, out, B);
}

// round 3
// speedup vs baseline: 2.6989x; 2.6989x over previous
#include <cuda_runtime.h>

// ExodusNet: per-timestep dense (32 -> 1), ExpLeak scan, LIF scan with
// SingleSpike + MembraneSubtract.  x: (B, 32, 100) fp32 (t innermost),
// w: (32) fp32, out: (B, 100) fp32 of 0/1 spikes.
//
// R3: identical compute structure to the 96us R1 kernel (float4 phase-1 loads,
// sequential f accumulation chain -> bitwise-stable numerics), but BPB halved
// 128 -> 64 so grid doubles to 512: ~2x resident warps/SM, ~2x in-flight
// DRAM bytes, smaller wave-imbalance tail.

namespace {

constexpr int T_STEPS    = 100;
constexpr int F_DIM      = 32;
constexpr int ROW_FLOATS = F_DIM * T_STEPS;       // 3200 floats per batch row
constexpr int BPB        = 64;                    // batch elements per block
constexpr int THREADS    = 256;                   // 8 warps
constexpr int B_PER_WARP = BPB / (THREADS / 32);  // 8
constexpr int SM_STRIDE  = 101;                   // conflict-free phase-2 reads

__device__ __forceinline__ float alpha_f() { return (float)0.9048374180359595; }
__device__ __forceinline__ float one_m_a() { return (float)(1.0 - 0.9048374180359595); }

__global__ __launch_bounds__(THREADS)
void exodus_kernel(const float* __restrict__ x,
                   const float* __restrict__ w,
                   float* __restrict__ out,
                   int B)
{
    __shared__ float wsh[F_DIM];
    extern __shared__ float ish[];                // BPB * SM_STRIDE floats

    const int tid  = threadIdx.x;
    const int warp = tid >> 5;
    const int lane = tid & 31;
    const int b0   = blockIdx.x * BPB;

    if (tid < F_DIM) wsh[tid] = w[tid];
    __syncthreads();

    // ---------------- Phase 1: weighted input currents i[b][t] ----------------
    // Warp-per-b; lanes 0..24 each own 4 consecutive timesteps (float4).
    // Per (b, f): one coalesced LDG.128 across 25 lanes.  float4 destinations
    // force ptxas to batch the loads (4 chain inputs per scoreboard slot),
    // keeping ~10 LDG.128 in flight per warp.
    {
        const int bl_begin = warp * B_PER_WARP;
        for (int bl = bl_begin; bl < bl_begin + B_PER_WARP; ++bl) {
            const int b = b0 + bl;
            if (b >= B) break;
            if (lane < 25) {
                const float* base = x + (size_t)b * ROW_FLOATS + 4 * lane;
                float4 acc = make_float4(0.f, 0.f, 0.f, 0.f);
                #pragma unroll
                for (int f = 0; f < F_DIM; ++f) {
                    const float4 xa = *reinterpret_cast<const float4*>(base + f * T_STEPS);
                    const float wf = wsh[f];
                    acc.x = fmaf(xa.x, wf, acc.x);
                    acc.y = fmaf(xa.y, wf, acc.y);
                    acc.z = fmaf(xa.z, wf, acc.z);
                    acc.w = fmaf(xa.w, wf, acc.w);
                }
                float* ip = ish + bl * SM_STRIDE + 4 * lane;
                ip[0] = acc.x;
                ip[1] = acc.y;
                ip[2] = acc.z;
                ip[3] = acc.w;
            }
        }
    }
    __syncthreads();

    // ---------------- Phase 2: sequential scans, one thread per b --------------
    // syn[t] = a*syn[t-1] + i[t]
    // v[t]   = a*v[t-1] + (1-a)*syn[t];  s = (v >= 1);  v -= s
    if (tid < BPB && (b0 + tid) < B) {
        float* ip = ish + tid * SM_STRIDE;
        float syn = 0.f, v = 0.f;
        #pragma unroll 4
        for (int t = 0; t < T_STEPS; ++t) {
            const float i = ip[t];
            syn = fmaf(alpha_f(), syn, i);
            v   = fmaf(alpha_f(), v, one_m_a() * syn);
            const float s = (v >= 1.0f) ? 1.0f : 0.0f;
            v -= s;
            ip[t] = s;
        }
    }
    __syncthreads();

    // ---------------- Phase 3: coalesced spike write-out -----------------------
    {
        const int bl_begin = warp * B_PER_WARP;
        for (int bl = bl_begin; bl < bl_begin + B_PER_WARP; ++bl) {
            const int b = b0 + bl;
            if (b >= B) break;
            float* op       = out + (size_t)b * T_STEPS;
            const float* ip = ish + bl * SM_STRIDE;
            #pragma unroll
            for (int j = 0; j < 4; ++j) {
                const int t = lane + 32 * j;
                if (t < T_STEPS) op[t] = ip[t];
            }
        }
    }
}

} // namespace

extern "C" void kernel_launch(void* const* d_in, const int* in_sizes, int n_in,
                              void* d_out, int out_size)
{
    const float* x = (const float*)d_in[0];
    const float* w = (const float*)d_in[1];
    float* out     = (float*)d_out;

    const int B = in_sizes[0] / ROW_FLOATS;   // 32768

    const int smem_bytes = BPB * SM_STRIDE * (int)sizeof(float);  // 25856
    cudaFuncSetAttribute(exodus_kernel,
                         cudaFuncAttributeMaxDynamicSharedMemorySize, smem_bytes);

    const int grid = (B + BPB - 1) / BPB;
    exodus_kernel<<<grid, THREADS, smem_bytes>>>(x, w, out, B);
}